// round 6
// baseline (speedup 1.0000x reference)
#include <cuda_runtime.h>
#include <cstdint>

// Problem constants
#define BB 2
#define NN 2048
#define MM 32
#define HH 8
#define DD 64
#define EE 512
#define FF 512
#define PP 6

// Scratch for projected Q and K: (B*N, E) fp32 each = 8 MB each
__device__ __align__(16) float g_Q[BB * NN * EE];
__device__ __align__(16) float g_K[BB * NN * EE];

// ---- packed f32x2 helpers (sm_103a FFMA2 path) ----
__device__ __forceinline__ unsigned long long ffma2(unsigned long long a,
                                                    unsigned long long b,
                                                    unsigned long long c)
{
    unsigned long long d;
    asm("fma.rn.f32x2 %0, %1, %2, %3;" : "=l"(d) : "l"(a), "l"(b), "l"(c));
    return d;
}
__device__ __forceinline__ unsigned long long dup2(float x)
{
    unsigned long long d;
    asm("mov.b64 %0, {%1, %1};" : "=l"(d) : "f"(x));
    return d;
}

// ---------------------------------------------------------------------------
// GEMM: C[4096 x 512] = A[4096 x 512] @ W[512 x 512], fp32 (FFMA2 inner loop).
// blockIdx.z = 0 -> (qf, Wq, g_Q); = 1 -> (kf, Wk, g_K)
// 128x128 block tile, BK=8, 256 threads, 8x8 per-thread microtile with
// accumulators packed pairwise along columns. Double-buffered smem,
// register prefetch, one barrier per k-slab.
// Issue model @occ2: fma-pipe 256 cyc/kk/SMSP binding; MOV dups + LDS (176
// issues) hide in FFMA2 rt-2 gaps -> ~FFMA2 roofline (~63 us both GEMMs).
// ---------------------------------------------------------------------------
__global__ __launch_bounds__(256, 2)
void gemm_kernel(const float* __restrict__ qf, const float* __restrict__ kf,
                 const float* __restrict__ Wq, const float* __restrict__ Wk)
{
    const float* A = (blockIdx.z == 0) ? qf : kf;
    const float* W = (blockIdx.z == 0) ? Wq : Wk;
    float* C = (blockIdx.z == 0) ? g_Q : g_K;

    __shared__ float As[2][8][132];   // transposed A tile, padded
    __shared__ float Bs[2][8][128];

    const int t = threadIdx.x;
    const int w = t >> 5;             // warp 0..7
    const int l = t & 31;
    const int wy = w >> 2;            // 0..1   (64-row slab)
    const int wx = w & 3;             // 0..3   (32-col slab)
    const int ly = l >> 2;            // 0..7
    const int lx = l & 3;             // 0..3
    const int rowT = wy * 64 + ly * 8;    // thread row within 128-tile
    const int colT = wx * 32 + lx * 8;    // thread col within 128-tile

    const int rowBase = blockIdx.y * 128;
    const int colBase = blockIdx.x * 128;

    // A tile load mapping: 128 rows x 8 k = 256 float4; 1 per thread
    const int a_row  = t >> 1;        // 0..127
    const int a_col4 = t & 1;
    // B tile load mapping: 8 rows x 128 cols = 256 float4; 1 per thread
    const int b_row = t >> 5;         // 0..7
    const int b_col = (t & 31) << 2;

    const float4* A4 = (const float4*)A;
    const float4* W4 = (const float4*)W;

    unsigned long long acc[8][4];
    #pragma unroll
    for (int i = 0; i < 8; i++)
        #pragma unroll
        for (int j = 0; j < 4; j++) acc[i][j] = 0ull;  // (0.f, 0.f)

    // prologue: load k-slab 0 into buffer 0
    {
        float4 av = A4[(rowBase + a_row) * (FF / 4) + a_col4];
        float4 bv = W4[b_row * (EE / 4) + (colBase >> 2) + (t & 31)];
        As[0][a_col4 * 4 + 0][a_row] = av.x;
        As[0][a_col4 * 4 + 1][a_row] = av.y;
        As[0][a_col4 * 4 + 2][a_row] = av.z;
        As[0][a_col4 * 4 + 3][a_row] = av.w;
        *(float4*)&Bs[0][b_row][b_col] = bv;
    }
    __syncthreads();

    int cur = 0;
    for (int k0 = 0; k0 < FF; k0 += 8) {
        const int nxt = k0 + 8;
        float4 av, bv;
        if (nxt < FF) {
            av = A4[(rowBase + a_row) * (FF / 4) + (nxt >> 2) + a_col4];
            bv = W4[(nxt + b_row) * (EE / 4) + (colBase >> 2) + (t & 31)];
        }

        #pragma unroll
        for (int kk = 0; kk < 8; kk++) {
            float4 a0 = *(const float4*)&As[cur][kk][rowT];
            float4 a1 = *(const float4*)&As[cur][kk][rowT + 4];
            const unsigned long long* bp =
                (const unsigned long long*)&Bs[cur][kk][colT];
            unsigned long long b0 = bp[0], b1 = bp[1], b2 = bp[2], b3 = bp[3];

            unsigned long long ad[8];
            ad[0] = dup2(a0.x); ad[1] = dup2(a0.y);
            ad[2] = dup2(a0.z); ad[3] = dup2(a0.w);
            ad[4] = dup2(a1.x); ad[5] = dup2(a1.y);
            ad[6] = dup2(a1.z); ad[7] = dup2(a1.w);

            #pragma unroll
            for (int i = 0; i < 8; i++) {
                acc[i][0] = ffma2(ad[i], b0, acc[i][0]);
                acc[i][1] = ffma2(ad[i], b1, acc[i][1]);
                acc[i][2] = ffma2(ad[i], b2, acc[i][2]);
                acc[i][3] = ffma2(ad[i], b3, acc[i][3]);
            }
        }

        if (nxt < FF) {
            const int nb = cur ^ 1;
            As[nb][a_col4 * 4 + 0][a_row] = av.x;
            As[nb][a_col4 * 4 + 1][a_row] = av.y;
            As[nb][a_col4 * 4 + 2][a_row] = av.z;
            As[nb][a_col4 * 4 + 3][a_row] = av.w;
            *(float4*)&Bs[nb][b_row][b_col] = bv;
            __syncthreads();
            cur = nb;
        }
    }

    #pragma unroll
    for (int i = 0; i < 8; i++) {
        float2 p0 = *(float2*)&acc[i][0];
        float2 p1 = *(float2*)&acc[i][1];
        float2 p2 = *(float2*)&acc[i][2];
        float2 p3 = *(float2*)&acc[i][3];
        float4* Crow = (float4*)&C[(rowBase + rowT + i) * EE + colBase + colT];
        Crow[0] = make_float4(p0.x, p0.y, p1.x, p1.y);
        Crow[1] = make_float4(p2.x, p2.y, p3.x, p3.y);
    }
}

// ---------------------------------------------------------------------------
// Attention-bias kernel. One block (256 thr) per (b, n).
//   content[m,h] = Q[bn,h,:]·K[b,idx[m],h,:]
//   pos[m,h]     = sum_p pl[m,p] * WlP[p,h],  WlP[p,h] = Wl[p,h,:]·(Q[bn,h,:]+v[h,:])
//   kb[h]        = K[bn,h,:]·u[h,:]
//   out = (content + pos + kb) / 8
// Warp w handles m in [4w, 4w+4). Each lane holds 16 Q floats + 16 K floats;
// 16-lane shfl_xor reductions produce one output per lane. Warp's 32 output
// words form one contiguous (lane-permuted) 128B block -> fully coalesced.
// NOTE: min-blocks=2 (NOT 8): the kr[4][4] fragment needs ~100 regs/thread;
// forcing 8 CTAs/SM would cap at 32 regs and spill the whole gather to local.
// ---------------------------------------------------------------------------
__global__ __launch_bounds__(256, 2)
void attn_kernel(const float* __restrict__ pl,   // (B,N,M,P)
                 const int*   __restrict__ nbhd, // (B,N,M)
                 const float* __restrict__ Wl,   // (P,E)
                 const float* __restrict__ u,    // (H,1,D) = 512 floats
                 const float* __restrict__ v,    // (H,1,D) = 512 floats
                 float* __restrict__ out)        // (B,N,M,H)
{
    __shared__ float pls[MM * PP];   // 192
    __shared__ float WlPs[PP * HH];  // 48
    __shared__ float kbs[HH];        // 8
    __shared__ int   idxs[MM];       // 32

    const int bn = blockIdx.x;
    const int b  = bn >> 11;         // bn / N
    const int t  = threadIdx.x;
    const int w  = t >> 5;
    const int l  = t & 31;

    if (t < MM * PP) pls[t] = pl[bn * (MM * PP) + t];
    if (t < MM)      idxs[t] = nbhd[bn * MM + t];
    __syncthreads();

    const float4* gQ4 = (const float4*)g_Q;
    const float4* gK4 = (const float4*)g_K;

    // Per-lane Q fragment: q[i] holds Q[bn, (i*32+l)*4 .. +3]
    float4 q[4];
    #pragma unroll
    for (int i = 0; i < 4; i++) q[i] = gQ4[bn * 128 + i * 32 + l];

    // Gather 4 K rows for this warp (coalesced float4 loads, high MLP)
    float4 kr[4][4];
    #pragma unroll
    for (int j = 0; j < 4; j++) {
        const int row = idxs[w * 4 + j];
        const long base = (long)(b * NN + row) * 128;
        #pragma unroll
        for (int i = 0; i < 4; i++) kr[j][i] = gK4[base + i * 32 + l];
    }

    // WlP precompute (threads 0..47) and key_bias (threads 48..55).
    // All base offsets are multiples of 64 floats -> float4-aligned.
    if (t < PP * HH) {
        const int p = t >> 3, h = t & 7;
        const float4* wrow = (const float4*)(Wl + p * EE + h * DD);
        const float4* qrow = (const float4*)(g_Q + bn * EE + h * DD);
        const float4* vrow = (const float4*)(v + h * DD);
        float s = 0.f;
        #pragma unroll
        for (int d4 = 0; d4 < DD / 4; d4++) {
            float4 wv = wrow[d4], qv = qrow[d4], vv = vrow[d4];
            s += wv.x * (qv.x + vv.x) + wv.y * (qv.y + vv.y)
               + wv.z * (qv.z + vv.z) + wv.w * (qv.w + vv.w);
        }
        WlPs[p * HH + h] = s;
    } else if (t < PP * HH + HH) {
        const int h = t - PP * HH;
        const float4* krow = (const float4*)(g_K + bn * EE + h * DD);
        const float4* urow = (const float4*)(u + h * DD);
        float s = 0.f;
        #pragma unroll
        for (int d4 = 0; d4 < DD / 4; d4++) {
            float4 kv = krow[d4], uv = urow[d4];
            s += kv.x * uv.x + kv.y * uv.y + kv.z * uv.z + kv.w * uv.w;
        }
        kbs[h] = s;
    }

    // Content: per m_j, s_i (after 16-lane reduction) = content for
    // h = 2*i + (lane>=16). Each lane keeps the value for its target (m,h).
    float cont = 0.f;
    #pragma unroll
    for (int j = 0; j < 4; j++) {
        float s0, s1, s2, s3;
        {
            float4 kv, qv;
            kv = kr[j][0]; qv = q[0];
            s0 = kv.x * qv.x + kv.y * qv.y + kv.z * qv.z + kv.w * qv.w;
            kv = kr[j][1]; qv = q[1];
            s1 = kv.x * qv.x + kv.y * qv.y + kv.z * qv.z + kv.w * qv.w;
            kv = kr[j][2]; qv = q[2];
            s2 = kv.x * qv.x + kv.y * qv.y + kv.z * qv.z + kv.w * qv.w;
            kv = kr[j][3]; qv = q[3];
            s3 = kv.x * qv.x + kv.y * qv.y + kv.z * qv.z + kv.w * qv.w;
        }
        #pragma unroll
        for (int st = 1; st <= 8; st <<= 1) {
            s0 += __shfl_xor_sync(0xFFFFFFFFu, s0, st);
            s1 += __shfl_xor_sync(0xFFFFFFFFu, s1, st);
            s2 += __shfl_xor_sync(0xFFFFFFFFu, s2, st);
            s3 += __shfl_xor_sync(0xFFFFFFFFu, s3, st);
        }
        if ((l & 3) == j) {
            const int it = (l >> 2) & 3;
            const float sel = (it == 0) ? s0 : (it == 1) ? s1 : (it == 2) ? s2 : s3;
            cont = sel;
        }
    }

    __syncthreads();  // WlPs / kbs visible

    const int m_t = l & 3;
    const int i_t = (l >> 2) & 3;
    const int h_t = 2 * i_t + (l >> 4);
    const int m   = w * 4 + m_t;

    float pos = 0.f;
    #pragma unroll
    for (int p = 0; p < PP; p++)
        pos += pls[m * PP + p] * WlPs[p * HH + h_t];

    out[bn * (MM * HH) + w * 32 + m_t * HH + h_t] =
        (cont + pos + kbs[h_t]) * 0.125f;
}

// ---------------------------------------------------------------------------
// Inputs (metadata order):
// 0 pairwise_locations (B,N,M,P) f32 | 1 mask (unused) | 2 query_features
// 3 key_features | 4 nbhd_idx i32 | 5 Wq | 6 Wk | 7 Wl | 8 u | 9 v
// Output: A (B,N,M,H) f32
// ---------------------------------------------------------------------------
extern "C" void kernel_launch(void* const* d_in, const int* in_sizes, int n_in,
                              void* d_out, int out_size)
{
    (void)in_sizes; (void)n_in; (void)out_size;
    const float* pl   = (const float*)d_in[0];
    const float* qf   = (const float*)d_in[2];
    const float* kf   = (const float*)d_in[3];
    const int*   nbhd = (const int*)  d_in[4];
    const float* Wq   = (const float*)d_in[5];
    const float* Wk   = (const float*)d_in[6];
    const float* Wl   = (const float*)d_in[7];
    const float* u    = (const float*)d_in[8];
    const float* v    = (const float*)d_in[9];
    float* out = (float*)d_out;

    dim3 ggrid(EE / 128, (BB * NN) / 128, 2);
    gemm_kernel<<<ggrid, 256>>>(qf, kf, Wq, Wk);
    attn_kernel<<<BB * NN, 256>>>(pl, nbhd, Wl, u, v, out);
}

// round 9
// speedup vs baseline: 1.2876x; 1.2876x over previous
#include <cuda_runtime.h>
#include <cstdint>

// Problem constants
#define BB 2
#define NN 2048
#define MM 32
#define HH 8
#define DD 64
#define EE 512
#define FF 512
#define PP 6

// Scratch for projected Q and K: (B*N, E) fp32 each = 8 MB each
__device__ __align__(16) float g_Q[BB * NN * EE];
__device__ __align__(16) float g_K[BB * NN * EE];

// ---- packed f32x2 helpers (sm_103a FFMA2 path) ----
__device__ __forceinline__ unsigned long long ffma2(unsigned long long a,
                                                    unsigned long long b,
                                                    unsigned long long c)
{
    unsigned long long d;
    asm("fma.rn.f32x2 %0, %1, %2, %3;" : "=l"(d) : "l"(a), "l"(b), "l"(c));
    return d;
}
__device__ __forceinline__ unsigned long long dup2(float x)
{
    unsigned long long d;
    asm("mov.b64 %0, {%1, %1};" : "=l"(d) : "f"(x));
    return d;
}

// ---------------------------------------------------------------------------
// GEMM: C[4096 x 512] = A[4096 x 512] @ W[512 x 512], fp32 (FFMA2 inner loop).
// Measured ~81 us for both GEMMs = 27 T-FMA/s = ~75% of packed-fp32 peak
// (above the 18 T-FMA/s scalar ceiling -> FFMA2 confirmed emitted).
// Next lever is tensor cores, deferred until the attn fix is confirmed.
// ---------------------------------------------------------------------------
__global__ __launch_bounds__(256, 2)
void gemm_kernel(const float* __restrict__ qf, const float* __restrict__ kf,
                 const float* __restrict__ Wq, const float* __restrict__ Wk)
{
    const float* A = (blockIdx.z == 0) ? qf : kf;
    const float* W = (blockIdx.z == 0) ? Wq : Wk;
    float* C = (blockIdx.z == 0) ? g_Q : g_K;

    __shared__ float As[2][8][132];   // transposed A tile, padded
    __shared__ float Bs[2][8][128];

    const int t = threadIdx.x;
    const int w = t >> 5;
    const int l = t & 31;
    const int wy = w >> 2;
    const int wx = w & 3;
    const int ly = l >> 2;
    const int lx = l & 3;
    const int rowT = wy * 64 + ly * 8;
    const int colT = wx * 32 + lx * 8;

    const int rowBase = blockIdx.y * 128;
    const int colBase = blockIdx.x * 128;

    const int a_row  = t >> 1;
    const int a_col4 = t & 1;
    const int b_row = t >> 5;
    const int b_col = (t & 31) << 2;

    const float4* A4 = (const float4*)A;
    const float4* W4 = (const float4*)W;

    unsigned long long acc[8][4];
    #pragma unroll
    for (int i = 0; i < 8; i++)
        #pragma unroll
        for (int j = 0; j < 4; j++) acc[i][j] = 0ull;

    {
        float4 av = A4[(rowBase + a_row) * (FF / 4) + a_col4];
        float4 bv = W4[b_row * (EE / 4) + (colBase >> 2) + (t & 31)];
        As[0][a_col4 * 4 + 0][a_row] = av.x;
        As[0][a_col4 * 4 + 1][a_row] = av.y;
        As[0][a_col4 * 4 + 2][a_row] = av.z;
        As[0][a_col4 * 4 + 3][a_row] = av.w;
        *(float4*)&Bs[0][b_row][b_col] = bv;
    }
    __syncthreads();

    int cur = 0;
    for (int k0 = 0; k0 < FF; k0 += 8) {
        const int nxt = k0 + 8;
        float4 av, bv;
        if (nxt < FF) {
            av = A4[(rowBase + a_row) * (FF / 4) + (nxt >> 2) + a_col4];
            bv = W4[(nxt + b_row) * (EE / 4) + (colBase >> 2) + (t & 31)];
        }

        #pragma unroll
        for (int kk = 0; kk < 8; kk++) {
            float4 a0 = *(const float4*)&As[cur][kk][rowT];
            float4 a1 = *(const float4*)&As[cur][kk][rowT + 4];
            const unsigned long long* bp =
                (const unsigned long long*)&Bs[cur][kk][colT];
            unsigned long long b0 = bp[0], b1 = bp[1], b2 = bp[2], b3 = bp[3];

            unsigned long long ad[8];
            ad[0] = dup2(a0.x); ad[1] = dup2(a0.y);
            ad[2] = dup2(a0.z); ad[3] = dup2(a0.w);
            ad[4] = dup2(a1.x); ad[5] = dup2(a1.y);
            ad[6] = dup2(a1.z); ad[7] = dup2(a1.w);

            #pragma unroll
            for (int i = 0; i < 8; i++) {
                acc[i][0] = ffma2(ad[i], b0, acc[i][0]);
                acc[i][1] = ffma2(ad[i], b1, acc[i][1]);
                acc[i][2] = ffma2(ad[i], b2, acc[i][2]);
                acc[i][3] = ffma2(ad[i], b3, acc[i][3]);
            }
        }

        if (nxt < FF) {
            const int nb = cur ^ 1;
            As[nb][a_col4 * 4 + 0][a_row] = av.x;
            As[nb][a_col4 * 4 + 1][a_row] = av.y;
            As[nb][a_col4 * 4 + 2][a_row] = av.z;
            As[nb][a_col4 * 4 + 3][a_row] = av.w;
            *(float4*)&Bs[nb][b_row][b_col] = bv;
            __syncthreads();
            cur = nb;
        }
    }

    #pragma unroll
    for (int i = 0; i < 8; i++) {
        float2 p0 = *(float2*)&acc[i][0];
        float2 p1 = *(float2*)&acc[i][1];
        float2 p2 = *(float2*)&acc[i][2];
        float2 p3 = *(float2*)&acc[i][3];
        float4* Crow = (float4*)&C[(rowBase + rowT + i) * EE + colBase + colT];
        Crow[0] = make_float4(p0.x, p0.y, p1.x, p1.y);
        Crow[1] = make_float4(p2.x, p2.y, p3.x, p3.y);
    }
}

// ---------------------------------------------------------------------------
// Attention-bias kernel, one block (256 thr) per (b, n).
// R6 change (evidence: ncu L1=60.6%, ~78% of L1 wavefronts were the
// uncoalesced 2-warp WlP/kb precompute):
//   * Q row staged via smem once (16 wf, was 128 redundant)
//   * WlP/kb precompute is warp-per-head: warp w=h does lane-coalesced
//     float2 loads of Q/Wl/K/u rows + 7 shfl-tree reductions.
// Predicted: 93.8 us -> ~22-28 us (L1 wf/CTA 3260 -> ~710, gather-bound).
// ---------------------------------------------------------------------------
__global__ __launch_bounds__(256, 2)
void attn_kernel(const float* __restrict__ pl,   // (B,N,M,P)
                 const int*   __restrict__ nbhd, // (B,N,M)
                 const float* __restrict__ Wl,   // (P,E)
                 const float* __restrict__ u,    // (H,1,D) = 512 floats
                 const float* __restrict__ v,    // (H,1,D) = 512 floats
                 float* __restrict__ out)        // (B,N,M,H)
{
    __shared__ float4 qs4[128];      // Q row (512 floats)
    __shared__ float pls[MM * PP];   // 192
    __shared__ float WlPs[PP * HH];  // 48
    __shared__ float kbs[HH];        // 8
    __shared__ int   idxs[MM];       // 32

    const int bn = blockIdx.x;
    const int b  = bn >> 11;         // bn / N
    const int t  = threadIdx.x;
    const int w  = t >> 5;
    const int l  = t & 31;

    if (t < MM * PP) pls[t] = pl[bn * (MM * PP) + t];
    if (t < MM)      idxs[t] = nbhd[bn * MM + t];
    if (t < 128)     qs4[t] = ((const float4*)g_Q)[bn * 128 + t];
    __syncthreads();

    const float4* gK4 = (const float4*)g_K;

    // Per-lane Q fragment from smem (conflict-free: 16B-stride phases)
    float4 q[4];
    #pragma unroll
    for (int i = 0; i < 4; i++) q[i] = qs4[i * 32 + l];

    // Gather 4 K rows for this warp (coalesced float4 loads, high MLP)
    float4 kr[4][4];
    #pragma unroll
    for (int j = 0; j < 4; j++) {
        const int row = idxs[w * 4 + j];
        const long base = (long)(b * NN + row) * 128;
        #pragma unroll
        for (int i = 0; i < 4; i++) kr[j][i] = gK4[base + i * 32 + l];
    }

    // ---- warp-per-head precompute: warp w handles h = w ----
    // s[p] = Wl[p,h,:]·(Q[bn,h,:]+v[h,:]) for p=0..5;  s[6] = K[bn,h,:]·u[h,:]
    {
        const int h = w;
        const float2 qv2 = ((const float2*)(g_Q + bn * EE + h * DD))[l];
        const float2 vv2 = ((const float2*)(v + h * DD))[l];
        const float2 kv2 = ((const float2*)(g_K + bn * EE + h * DD))[l];
        const float2 uv2 = ((const float2*)(u + h * DD))[l];
        const float qpv0 = qv2.x + vv2.x;
        const float qpv1 = qv2.y + vv2.y;

        float s[7];
        #pragma unroll
        for (int p = 0; p < PP; p++) {
            const float2 wv2 = ((const float2*)(Wl + p * EE + h * DD))[l];
            s[p] = wv2.x * qpv0 + wv2.y * qpv1;
        }
        s[6] = kv2.x * uv2.x + kv2.y * uv2.y;

        #pragma unroll
        for (int st = 16; st >= 1; st >>= 1)
            #pragma unroll
            for (int i = 0; i < 7; i++)
                s[i] += __shfl_xor_sync(0xFFFFFFFFu, s[i], st);

        if (l == 0) {
            #pragma unroll
            for (int p = 0; p < PP; p++) WlPs[p * HH + h] = s[p];
            kbs[h] = s[6];
        }
    }

    // Content: per m_j, s_i (after 16-lane reduction) = content for
    // h = 2*i + (lane>=16). Each lane keeps the value for its target (m,h).
    float cont = 0.f;
    #pragma unroll
    for (int j = 0; j < 4; j++) {
        float s0, s1, s2, s3;
        {
            float4 kv, qv;
            kv = kr[j][0]; qv = q[0];
            s0 = kv.x * qv.x + kv.y * qv.y + kv.z * qv.z + kv.w * qv.w;
            kv = kr[j][1]; qv = q[1];
            s1 = kv.x * qv.x + kv.y * qv.y + kv.z * qv.z + kv.w * qv.w;
            kv = kr[j][2]; qv = q[2];
            s2 = kv.x * qv.x + kv.y * qv.y + kv.z * qv.z + kv.w * qv.w;
            kv = kr[j][3]; qv = q[3];
            s3 = kv.x * qv.x + kv.y * qv.y + kv.z * qv.z + kv.w * qv.w;
        }
        #pragma unroll
        for (int st = 1; st <= 8; st <<= 1) {
            s0 += __shfl_xor_sync(0xFFFFFFFFu, s0, st);
            s1 += __shfl_xor_sync(0xFFFFFFFFu, s1, st);
            s2 += __shfl_xor_sync(0xFFFFFFFFu, s2, st);
            s3 += __shfl_xor_sync(0xFFFFFFFFu, s3, st);
        }
        if ((l & 3) == j) {
            const int it = (l >> 2) & 3;
            const float sel = (it == 0) ? s0 : (it == 1) ? s1 : (it == 2) ? s2 : s3;
            cont = sel;
        }
    }

    __syncthreads();  // WlPs / kbs visible

    const int m_t = l & 3;
    const int i_t = (l >> 2) & 3;
    const int h_t = 2 * i_t + (l >> 4);
    const int m   = w * 4 + m_t;

    float pos = 0.f;
    #pragma unroll
    for (int p = 0; p < PP; p++)
        pos += pls[m * PP + p] * WlPs[p * HH + h_t];

    out[bn * (MM * HH) + w * 32 + m_t * HH + h_t] =
        (cont + pos + kbs[h_t]) * 0.125f;
}

// ---------------------------------------------------------------------------
// Inputs (metadata order):
// 0 pairwise_locations (B,N,M,P) f32 | 1 mask (unused) | 2 query_features
// 3 key_features | 4 nbhd_idx i32 | 5 Wq | 6 Wk | 7 Wl | 8 u | 9 v
// Output: A (B,N,M,H) f32
// ---------------------------------------------------------------------------
extern "C" void kernel_launch(void* const* d_in, const int* in_sizes, int n_in,
                              void* d_out, int out_size)
{
    (void)in_sizes; (void)n_in; (void)out_size;
    const float* pl   = (const float*)d_in[0];
    const float* qf   = (const float*)d_in[2];
    const float* kf   = (const float*)d_in[3];
    const int*   nbhd = (const int*)  d_in[4];
    const float* Wq   = (const float*)d_in[5];
    const float* Wk   = (const float*)d_in[6];
    const float* Wl   = (const float*)d_in[7];
    const float* u    = (const float*)d_in[8];
    const float* v    = (const float*)d_in[9];
    float* out = (float*)d_out;

    dim3 ggrid(EE / 128, (BB * NN) / 128, 2);
    gemm_kernel<<<ggrid, 256>>>(qf, kf, Wq, Wk);
    attn_kernel<<<BB * NN, 256>>>(pl, nbhd, Wl, u, v, out);
}